// round 3
// baseline (speedup 1.0000x reference)
#include <cuda_runtime.h>
#include <math.h>
#include <float.h>

#define NGRAPH 1024
#define TOPK 32
#define BS 256
#define CAP 2048
#define NEG_MIN (-3.4028234663852886e38f)   // np.finfo(float32).min == -FLT_MAX

__device__ int g_seg_start[NGRAPH + 1];

// Order-preserving float->uint flip: larger float -> larger unsigned.
__device__ __forceinline__ unsigned flipf(float s) {
    unsigned u = __float_as_uint(s);
    return (u & 0x80000000u) ? ~u : (u | 0x80000000u);
}

// ---------------------------------------------------------------------------
// K1: segment starts via binary search over the sorted edge_batch.
// Dtype-robust: in an int64 buffer every odd 32-bit word is a zero high-half;
// in a sorted int32 buffer the last word is ~NG-1 > 0.
// ---------------------------------------------------------------------------
__global__ void seg_start_kernel(const int* __restrict__ b32, int E) {
    int g = blockIdx.x * blockDim.x + threadIdx.x;
    if (g > NGRAPH) return;
    if (g == 0)      { g_seg_start[0] = 0;       return; }
    if (g == NGRAPH) { g_seg_start[NGRAPH] = E;  return; }

    const int oddIdx = (E - 2) | 1;          // largest odd word index <= E-1
    const bool is64 = (b32[oddIdx] == 0);

    int lo = 0, hi = E;
    if (is64) {
        const long long* b = (const long long*)b32;
        const long long key = (long long)g;
        while (lo < hi) {
            int mid = (lo + hi) >> 1;
            if (b[mid] < key) lo = mid + 1; else hi = mid;
        }
    } else {
        while (lo < hi) {
            int mid = (lo + hi) >> 1;
            if (b32[mid] < g) lo = mid + 1; else hi = mid;
        }
    }
    g_seg_start[g] = lo;
}

// ---------------------------------------------------------------------------
// K2 (fused): per-graph exact top-K (stable tie-break: score desc, index asc),
// segmented log-denominator, output fill + kept-value write — all per block.
// ---------------------------------------------------------------------------
__global__ void __launch_bounds__(BS) topk_kernel(
    const float* __restrict__ logits,
    const float* __restrict__ scores,
    const float* __restrict__ stop,
    const int*   __restrict__ cmask,        // bool delivered as int32
    float* __restrict__ out)
{
    __shared__ int      hist[2048];
    __shared__ unsigned buf_fl[CAP];
    __shared__ int      buf_ix[CAP];
    __shared__ int      s_found, s_bin, s_above, s_cnt, s_minix;
    __shared__ unsigned s_Tf;
    __shared__ int      s_Tix;
    __shared__ int      s_kcnt;
    __shared__ int      s_kidx[TOPK];
    __shared__ float    s_lv[TOPK];
    __shared__ float    s_ld;

    const int g   = blockIdx.x;
    const int tid = threadIdx.x;
    const int s0 = g_seg_start[g];
    const int s1 = g_seg_start[g + 1];

    unsigned prefix = 0, pmask = 0;
    int  above   = 0;
    bool keepall = false, have_thr = false;

    // Multi-level radix select on flipped score bits: 11 + 11 + 10 bits.
    for (int lvl = 0; lvl < 3; ++lvl) {
        const int      shift = (lvl == 0) ? 21 : (lvl == 1) ? 10 : 0;
        const unsigned mw    = (lvl == 2) ? 0x3FFu : 0x7FFu;

        for (int j = tid; j < 2048; j += BS) hist[j] = 0;
        if (tid == 0) s_found = 0;
        __syncthreads();

        for (int i = s0 + tid; i < s1; i += BS) {
            if (cmask[i] != 0) {
                unsigned fl = flipf(scores[i]);
                if ((fl & pmask) == prefix)
                    atomicAdd(&hist[(fl >> shift) & mw], 1);
            }
        }
        __syncthreads();

        // Warp 0: descending cumulative scan over bins to find the bin
        // containing the Kp-th largest element of the current group.
        if (tid < 32) {
            const int lane = tid;
            const int Kp   = TOPK - above;
            int cum = 0;
            for (int base = (int)mw; base >= 0; base -= 32) {
                int bin = base - lane;
                int c   = (bin >= 0) ? hist[bin] : 0;
                int incl = c;
                #pragma unroll
                for (int off = 1; off < 32; off <<= 1) {
                    int v = __shfl_up_sync(0xffffffffu, incl, off);
                    if (lane >= off) incl += v;
                }
                unsigned bal = __ballot_sync(0xffffffffu, cum + incl >= Kp);
                if (bal) {
                    int first = __ffs(bal) - 1;
                    if (lane == first) { s_bin = bin; s_above = cum + incl - c; s_found = 1; }
                    break;                       // ballot is warp-uniform
                }
                cum += __shfl_sync(0xffffffffu, incl, 31);
            }
        }
        __syncthreads();

        if (!s_found) { keepall = true; break; } // total candidates < K (lvl 0 only)

        const int b = s_bin;
        above  += s_above;
        const int n = hist[b];
        prefix |= ((unsigned)b) << shift;
        pmask  |= mw << shift;
        __syncthreads();                         // hist reads done before next zeroing

        if (n <= CAP) {
            // Collect the candidate bin, then exact-rank inside it
            // (tie-break: score desc, index asc — matches stable argsort).
            if (tid == 0) s_cnt = 0;
            __syncthreads();
            for (int i = s0 + tid; i < s1; i += BS) {
                if (cmask[i] != 0) {
                    unsigned fl = flipf(scores[i]);
                    if ((fl & pmask) == prefix) {
                        int p = atomicAdd(&s_cnt, 1);
                        buf_fl[p] = fl; buf_ix[p] = i;
                    }
                }
            }
            __syncthreads();
            const int nn = s_cnt;
            const int r  = TOPK - 1 - above;     // rank of K-th element inside buffer
            for (int j = tid; j < nn; j += BS) {
                unsigned fj = buf_fl[j]; int ij = buf_ix[j];
                int rk = 0;
                for (int l = 0; l < nn; ++l) {
                    unsigned fl2 = buf_fl[l];
                    rk += (fl2 > fj) || (fl2 == fj && buf_ix[l] < ij);
                }
                if (rk == r) { s_Tf = fj; s_Tix = ij; }
            }
            have_thr = true;
            __syncthreads();
            break;
        }
    }

    unsigned Tf; int Tix;
    if (keepall)        { Tf = 0u;    Tix = 0x7FFFFFFF; }
    else if (have_thr)  { Tf = s_Tf;  Tix = s_Tix; }
    else {
        // >CAP exact 32-bit duplicates: prefix is the exact flipped value.
        // Keep the m smallest indices among the tied group (pathological path).
        const int m = TOPK - above;
        int last = -1;
        for (int t = 0; t < m; ++t) {
            if (tid == 0) s_minix = 0x7FFFFFFF;
            __syncthreads();
            for (int i = s0 + tid; i < s1; i += BS) {
                if (cmask[i] != 0 && i > last) {
                    if (flipf(scores[i]) == prefix) atomicMin(&s_minix, i);
                }
            }
            __syncthreads();
            last = s_minix;
            __syncthreads();
        }
        Tf = prefix; Tix = last;
    }

    // Final pass: exact keep predicate, collect kept edge indices.
    if (tid == 0) s_kcnt = 0;
    __syncthreads();
    for (int i = s0 + tid; i < s1; i += BS) {
        if (cmask[i] != 0) {
            unsigned fl = flipf(scores[i]);
            if (fl > Tf || (fl == Tf && i <= Tix)) {
                int p = atomicAdd(&s_kcnt, 1);
                if (p < TOPK) s_kidx[p] = i;
            }
        }
    }
    __syncthreads();
    const int kc = min(s_kcnt, TOPK);

    if (tid < kc) s_lv[tid] = logits[s_kidx[tid]];   // TEMP == 1.0
    __syncthreads();

    if (tid < 32) {
        float v = (tid < kc) ? s_lv[tid] : -INFINITY;
        float mx = v;
        #pragma unroll
        for (int off = 16; off; off >>= 1) mx = fmaxf(mx, __shfl_xor_sync(0xffffffffu, mx, off));
        float e = (tid < kc) ? expf(v - mx) : 0.0f;
        #pragma unroll
        for (int off = 16; off; off >>= 1) e += __shfl_xor_sync(0xffffffffu, e, off);
        if (tid == 0) {
            float st = stop[g];
            float ld;
            if (kc == 0) ld = st;
            else {
                float lse = logf(e) + mx;
                float a = fmaxf(lse, st), b2 = fminf(lse, st);
                ld = a + log1pf(expf(b2 - a));
            }
            s_ld = ld;
        }
    }
    __syncthreads();

    // Fill this block's output segment with finfo(f32).min (float4 body).
    {
        const int a4 = (s0 + 3) & ~3;            // first 16B-aligned element
        const int b4 = s1 & ~3;                  // end of aligned body
        for (int i = s0 + tid; i < a4 && i < s1; i += BS) out[i] = NEG_MIN;
        if (b4 > a4) {
            float4* o4 = (float4*)(out);
            const float4 v4 = make_float4(NEG_MIN, NEG_MIN, NEG_MIN, NEG_MIN);
            for (int i = (a4 >> 2) + tid; i < (b4 >> 2); i += BS) o4[i] = v4;
            for (int i = b4 + tid; i < s1; i += BS) out[i] = NEG_MIN;
        } else {
            for (int i = ((a4 > s0) ? a4 : s0) + tid; i < s1; i += BS)
                if (i >= a4) out[i] = NEG_MIN;
        }
    }
    __syncthreads();

    // Overwrite kept positions with their log-probs.
    if (tid < kc) out[s_kidx[tid]] = s_lv[tid] - s_ld;
}

extern "C" void kernel_launch(void* const* d_in, const int* in_sizes, int n_in,
                              void* d_out, int out_size) {
    const float* logits = (const float*)d_in[0];
    const float* scores = (const float*)d_in[1];
    const float* stop   = (const float*)d_in[2];
    const int*   batch  = (const int*)d_in[3];
    const int*   cmask  = (const int*)d_in[4];
    float* out = (float*)d_out;
    const int E = in_sizes[0];

    seg_start_kernel<<<(NGRAPH + 1 + 255) / 256, 256>>>(batch, E);
    topk_kernel<<<NGRAPH, BS>>>(logits, scores, stop, cmask, out);
}

// round 4
// speedup vs baseline: 2.1091x; 2.1091x over previous
#include <cuda_runtime.h>
#include <math.h>

#define NGRAPH 1024
#define TOPK 32
#define BS 256
#define CAP 2048
#define NEG_MIN (-3.4028234663852886e38f)   // np.finfo(float32).min == -FLT_MAX
#define FL0 0xC0000000u                      // flipf(2.0f): prior threshold ~2 sigma

// Order-preserving float->uint flip: larger float -> larger unsigned.
__device__ __forceinline__ unsigned flipf(float s) {
    unsigned u = __float_as_uint(s);
    return (u & 0x80000000u) ? ~u : (u | 0x80000000u);
}

// ---------------------------------------------------------------------------
// Fused kernel: per-block segment binary search, single fused scan
// (output fill + candidate collection above a prior threshold), exact in-smem
// top-K ranking (stable tie-break: score desc, index asc), segmented
// log-denominator, kept-value write. Full radix-select fallback for
// distributions where the prior threshold assumption fails.
// ---------------------------------------------------------------------------
__global__ void __launch_bounds__(BS) topk_kernel(
    const float* __restrict__ logits,
    const float* __restrict__ scores,
    const float* __restrict__ stop,
    const int*   __restrict__ cmask,        // bool delivered as int32
    const int*   __restrict__ b32,          // edge_batch (int32 or int64 words)
    float* __restrict__ out,
    int E)
{
    __shared__ int      seg[2];
    __shared__ unsigned buf_fl[CAP];
    __shared__ int      buf_ix[CAP];
    __shared__ int      s_cnt;
    __shared__ int      s_kidx[TOPK];
    __shared__ float    s_lv[TOPK];
    __shared__ float    s_ld;
    // fallback-only state
    __shared__ int      hist[2048];
    __shared__ int      s_found, s_bin, s_above, s_minix, s_kcnt;
    __shared__ unsigned s_Tf;
    __shared__ int      s_Tix;

    const int g   = blockIdx.x;
    const int tid = threadIdx.x;

    // Segment bounds: threads 0/1 binary-search lower bounds of g and g+1.
    if (tid < 2) {
        const int target = g + tid;
        int lo = 0;
        if (target == NGRAPH) lo = E;
        else if (target > 0) {
            // dtype sniff: int64 buffers have zero odd (high-half) words.
            const bool is64 = (b32[(E - 2) | 1] == 0);
            int hi = E;
            if (is64) {
                const long long* b = (const long long*)b32;
                const long long key = (long long)target;
                while (lo < hi) { int mid = (lo + hi) >> 1; if (b[mid] < key) lo = mid + 1; else hi = mid; }
            } else {
                while (lo < hi) { int mid = (lo + hi) >> 1; if (b32[mid] < target) lo = mid + 1; else hi = mid; }
            }
        }
        seg[tid] = lo;
    }
    if (tid == 0) s_cnt = 0;
    __syncthreads();
    const int s0 = seg[0], s1 = seg[1];

    // ---- Single fused pass: fill out[] with NEG_MIN, collect fl > FL0 ----
    {
        const float4 v4 = make_float4(NEG_MIN, NEG_MIN, NEG_MIN, NEG_MIN);
        int a4 = (s0 + 3) & ~3; if (a4 > s1) a4 = s1;
        int b4 = s1 & ~3;       if (b4 < a4) b4 = a4;

        for (int i = s0 + tid; i < a4; i += BS) {
            const int c = cmask[i];
            const unsigned fl = flipf(scores[i]);
            out[i] = NEG_MIN;
            if (c && fl > FL0) {
                int p = atomicAdd(&s_cnt, 1);
                if (p < CAP) { buf_fl[p] = fl; buf_ix[p] = i; }
            }
        }
        for (int i = a4 + tid * 4; i < b4; i += BS * 4) {
            const float4 sc = *(const float4*)(scores + i);
            const int4   cm = *(const int4*)(cmask + i);
            *(float4*)(out + i) = v4;
            unsigned fl;
            fl = flipf(sc.x); if (cm.x && fl > FL0) { int p = atomicAdd(&s_cnt, 1); if (p < CAP) { buf_fl[p] = fl; buf_ix[p] = i;     } }
            fl = flipf(sc.y); if (cm.y && fl > FL0) { int p = atomicAdd(&s_cnt, 1); if (p < CAP) { buf_fl[p] = fl; buf_ix[p] = i + 1; } }
            fl = flipf(sc.z); if (cm.z && fl > FL0) { int p = atomicAdd(&s_cnt, 1); if (p < CAP) { buf_fl[p] = fl; buf_ix[p] = i + 2; } }
            fl = flipf(sc.w); if (cm.w && fl > FL0) { int p = atomicAdd(&s_cnt, 1); if (p < CAP) { buf_fl[p] = fl; buf_ix[p] = i + 3; } }
        }
        for (int i = b4 + tid; i < s1; i += BS) {
            const int c = cmask[i];
            const unsigned fl = flipf(scores[i]);
            out[i] = NEG_MIN;
            if (c && fl > FL0) {
                int p = atomicAdd(&s_cnt, 1);
                if (p < CAP) { buf_fl[p] = fl; buf_ix[p] = i; }
            }
        }
    }
    __syncthreads();

    int kc;
    const int nhi = s_cnt;
    if (nhi >= TOPK && nhi <= CAP) {
        // ---- Fast path: exact top-K ranking inside the smem buffer ----
        // If >= K candidates exceed FL0, the global top-K all exceed FL0,
        // so they are all in the buffer. Rank by (fl desc, idx asc).
        for (int j = tid; j < nhi; j += BS) {
            const unsigned fj = buf_fl[j];
            const int      ij = buf_ix[j];
            int rk = 0;
            for (int l = 0; l < nhi; ++l) {
                const unsigned fl2 = buf_fl[l];
                rk += (fl2 > fj) || (fl2 == fj && buf_ix[l] < ij);
            }
            if (rk < TOPK) s_kidx[rk] = ij;
        }
        kc = TOPK;
        __syncthreads();
    } else {
        // ---- Fallback: exact 3-level radix select over the segment ----
        unsigned prefix = 0, pmask = 0;
        int  above = 0;
        bool keepall = false, have_thr = false;

        for (int lvl = 0; lvl < 3; ++lvl) {
            const int      shift = (lvl == 0) ? 21 : (lvl == 1) ? 10 : 0;
            const unsigned mw    = (lvl == 2) ? 0x3FFu : 0x7FFu;

            for (int j = tid; j < 2048; j += BS) hist[j] = 0;
            if (tid == 0) s_found = 0;
            __syncthreads();

            for (int i = s0 + tid; i < s1; i += BS) {
                if (cmask[i] != 0) {
                    unsigned fl = flipf(scores[i]);
                    if ((fl & pmask) == prefix)
                        atomicAdd(&hist[(fl >> shift) & mw], 1);
                }
            }
            __syncthreads();

            if (tid < 32) {
                const int lane = tid;
                const int Kp   = TOPK - above;
                int cum = 0;
                for (int base = (int)mw; base >= 0; base -= 32) {
                    int bin = base - lane;
                    int c   = (bin >= 0) ? hist[bin] : 0;
                    int incl = c;
                    #pragma unroll
                    for (int off = 1; off < 32; off <<= 1) {
                        int v = __shfl_up_sync(0xffffffffu, incl, off);
                        if (lane >= off) incl += v;
                    }
                    unsigned bal = __ballot_sync(0xffffffffu, cum + incl >= Kp);
                    if (bal) {
                        int first = __ffs(bal) - 1;
                        if (lane == first) { s_bin = bin; s_above = cum + incl - c; s_found = 1; }
                        break;
                    }
                    cum += __shfl_sync(0xffffffffu, incl, 31);
                }
            }
            __syncthreads();

            if (!s_found) { keepall = true; break; }

            const int b = s_bin;
            above  += s_above;
            const int n = hist[b];
            prefix |= ((unsigned)b) << shift;
            pmask  |= mw << shift;
            __syncthreads();

            if (n <= CAP) {
                if (tid == 0) s_kcnt = 0;
                __syncthreads();
                for (int i = s0 + tid; i < s1; i += BS) {
                    if (cmask[i] != 0) {
                        unsigned fl = flipf(scores[i]);
                        if ((fl & pmask) == prefix) {
                            int p = atomicAdd(&s_kcnt, 1);
                            buf_fl[p] = fl; buf_ix[p] = i;
                        }
                    }
                }
                __syncthreads();
                const int nn = s_kcnt;
                const int r  = TOPK - 1 - above;
                for (int j = tid; j < nn; j += BS) {
                    unsigned fj = buf_fl[j]; int ij = buf_ix[j];
                    int rk = 0;
                    for (int l = 0; l < nn; ++l) {
                        unsigned fl2 = buf_fl[l];
                        rk += (fl2 > fj) || (fl2 == fj && buf_ix[l] < ij);
                    }
                    if (rk == r) { s_Tf = fj; s_Tix = ij; }
                }
                have_thr = true;
                __syncthreads();
                break;
            }
        }

        unsigned Tf; int Tix;
        if (keepall)       { Tf = 0u;   Tix = 0x7FFFFFFF; }
        else if (have_thr) { Tf = s_Tf; Tix = s_Tix; }
        else {
            const int m = TOPK - above;
            int last = -1;
            for (int t = 0; t < m; ++t) {
                if (tid == 0) s_minix = 0x7FFFFFFF;
                __syncthreads();
                for (int i = s0 + tid; i < s1; i += BS) {
                    if (cmask[i] != 0 && i > last) {
                        if (flipf(scores[i]) == prefix) atomicMin(&s_minix, i);
                    }
                }
                __syncthreads();
                last = s_minix;
                __syncthreads();
            }
            Tf = prefix; Tix = last;
        }

        if (tid == 0) s_kcnt = 0;
        __syncthreads();
        for (int i = s0 + tid; i < s1; i += BS) {
            if (cmask[i] != 0) {
                unsigned fl = flipf(scores[i]);
                if (fl > Tf || (fl == Tf && i <= Tix)) {
                    int p = atomicAdd(&s_kcnt, 1);
                    if (p < TOPK) s_kidx[p] = i;
                }
            }
        }
        __syncthreads();
        kc = min(s_kcnt, TOPK);
    }

    // ---- Segmented log-denominator over the <=32 kept logits + stop ----
    if (tid < kc) s_lv[tid] = logits[s_kidx[tid]];   // TEMP == 1.0
    __syncthreads();

    if (tid < 32) {
        float v = (tid < kc) ? s_lv[tid] : -INFINITY;
        float mx = v;
        #pragma unroll
        for (int off = 16; off; off >>= 1) mx = fmaxf(mx, __shfl_xor_sync(0xffffffffu, mx, off));
        float e = (tid < kc) ? expf(v - mx) : 0.0f;
        #pragma unroll
        for (int off = 16; off; off >>= 1) e += __shfl_xor_sync(0xffffffffu, e, off);
        if (tid == 0) {
            float st = stop[g];
            float ld;
            if (kc == 0) ld = st;
            else {
                float lse = logf(e) + mx;
                float a = fmaxf(lse, st), b2 = fminf(lse, st);
                ld = a + log1pf(expf(b2 - a));
            }
            s_ld = ld;
        }
    }
    __syncthreads();

    // Overwrite kept positions (fill already happened in the fused pass).
    if (tid < kc) out[s_kidx[tid]] = s_lv[tid] - s_ld;
}

extern "C" void kernel_launch(void* const* d_in, const int* in_sizes, int n_in,
                              void* d_out, int out_size) {
    const float* logits = (const float*)d_in[0];
    const float* scores = (const float*)d_in[1];
    const float* stop   = (const float*)d_in[2];
    const int*   batch  = (const int*)d_in[3];
    const int*   cmask  = (const int*)d_in[4];
    float* out = (float*)d_out;
    const int E = in_sizes[0];

    topk_kernel<<<NGRAPH, BS>>>(logits, scores, stop, cmask, batch, out, E);
}

// round 5
// speedup vs baseline: 2.3029x; 1.0919x over previous
#include <cuda_runtime.h>
#include <math.h>

#define NGRAPH 1024
#define TOPK 32
#define BS 256
#define CAP 2048
#define NEG_MIN (-3.4028234663852886e38f)   // np.finfo(float32).min == -FLT_MAX
#define THR 2.0f                             // prior threshold ~2 sigma
#define FL0 0xC0000000u                      // flipf(2.0f)

// Order-preserving float->uint flip: larger float -> larger unsigned.
__device__ __forceinline__ unsigned flipf(float s) {
    unsigned u = __float_as_uint(s);
    return (u & 0x80000000u) ? ~u : (u | 0x80000000u);
}

// ---------------------------------------------------------------------------
// Fused kernel: per-block segment binary search, single high-MLP fused scan
// (output fill + candidate collection above a prior threshold), exact in-smem
// top-K ranking (stable tie-break: score desc, index asc), segmented
// log-denominator, kept-value write. Full radix-select fallback.
// ---------------------------------------------------------------------------
__global__ void __launch_bounds__(BS) topk_kernel(
    const float* __restrict__ logits,
    const float* __restrict__ scores,
    const float* __restrict__ stop,
    const int*   __restrict__ cmask,        // bool delivered as int32
    const int*   __restrict__ b32,          // edge_batch (int32 or int64 words)
    float* __restrict__ out,
    int E)
{
    __shared__ int      seg[2];
    __shared__ unsigned buf_fl[CAP];
    __shared__ int      buf_ix[CAP];
    __shared__ int      s_cnt;
    __shared__ int      s_kidx[TOPK];
    __shared__ float    s_lv[TOPK];
    __shared__ float    s_ld;
    // fallback-only state
    __shared__ int      hist[2048];
    __shared__ int      s_found, s_bin, s_above, s_minix, s_kcnt;
    __shared__ unsigned s_Tf;
    __shared__ int      s_Tix;

    const int g   = blockIdx.x;
    const int tid = threadIdx.x;

    // Segment bounds: threads 0/1 binary-search lower bounds of g and g+1.
    if (tid < 2) {
        const int target = g + tid;
        int lo = 0;
        if (target == NGRAPH) lo = E;
        else if (target > 0) {
            // dtype sniff: int64 buffers have zero odd (high-half) words.
            const bool is64 = (b32[(E - 2) | 1] == 0);
            int hi = E;
            if (is64) {
                const long long* b = (const long long*)b32;
                const long long key = (long long)target;
                while (lo < hi) { int mid = (lo + hi) >> 1; if (b[mid] < key) lo = mid + 1; else hi = mid; }
            } else {
                while (lo < hi) { int mid = (lo + hi) >> 1; if (b32[mid] < target) lo = mid + 1; else hi = mid; }
            }
        }
        seg[tid] = lo;
    }
    if (tid == 0) s_cnt = 0;
    __syncthreads();
    const int s0 = seg[0], s1 = seg[1];

    // ---- Single fused pass: fill out[] with NEG_MIN, collect score > THR ----
    {
        const float4 v4 = make_float4(NEG_MIN, NEG_MIN, NEG_MIN, NEG_MIN);
        int a4 = (s0 + 3) & ~3; if (a4 > s1) a4 = s1;
        int b4 = s1 & ~3;       if (b4 < a4) b4 = a4;

        for (int i = s0 + tid; i < a4; i += BS) {
            const int c = cmask[i];
            const float s = scores[i];
            out[i] = NEG_MIN;
            if (c && s > THR) {
                int p = atomicAdd(&s_cnt, 1);
                if (p < CAP) { buf_fl[p] = flipf(s); buf_ix[p] = i; }
            }
        }

        // Unrolled body: batch 8 LDG.128s before any dependent work.
        for (int base = a4 + tid * 4; base < b4; base += BS * 16) {
            float4 sc[4]; int4 cm[4]; bool ok[4]; int ii[4];
            #pragma unroll
            for (int u = 0; u < 4; ++u) {
                ii[u] = base + u * BS * 4;
                ok[u] = ii[u] < b4;
                if (ok[u]) {
                    sc[u] = __ldcs((const float4*)(scores + ii[u]));
                    cm[u] = __ldcs((const int4*)(cmask + ii[u]));
                }
            }
            #pragma unroll
            for (int u = 0; u < 4; ++u)
                if (ok[u]) __stcs((float4*)(out + ii[u]), v4);
            #pragma unroll
            for (int u = 0; u < 4; ++u) {
                if (!ok[u]) continue;
                const int i = ii[u];
                if (cm[u].x && sc[u].x > THR) { int p = atomicAdd(&s_cnt, 1); if (p < CAP) { buf_fl[p] = flipf(sc[u].x); buf_ix[p] = i;     } }
                if (cm[u].y && sc[u].y > THR) { int p = atomicAdd(&s_cnt, 1); if (p < CAP) { buf_fl[p] = flipf(sc[u].y); buf_ix[p] = i + 1; } }
                if (cm[u].z && sc[u].z > THR) { int p = atomicAdd(&s_cnt, 1); if (p < CAP) { buf_fl[p] = flipf(sc[u].z); buf_ix[p] = i + 2; } }
                if (cm[u].w && sc[u].w > THR) { int p = atomicAdd(&s_cnt, 1); if (p < CAP) { buf_fl[p] = flipf(sc[u].w); buf_ix[p] = i + 3; } }
            }
        }

        for (int i = b4 + tid; i < s1; i += BS) {
            const int c = cmask[i];
            const float s = scores[i];
            out[i] = NEG_MIN;
            if (c && s > THR) {
                int p = atomicAdd(&s_cnt, 1);
                if (p < CAP) { buf_fl[p] = flipf(s); buf_ix[p] = i; }
            }
        }
    }
    __syncthreads();

    int kc;
    const int nhi = s_cnt;
    if (nhi >= TOPK && nhi <= CAP) {
        // ---- Fast path: exact top-K ranking inside the smem buffer ----
        // If >= K candidates exceed THR, the global top-K all exceed THR,
        // so they are all in the buffer. Rank by (fl desc, idx asc).
        for (int j = tid; j < nhi; j += BS) {
            const unsigned fj = buf_fl[j];
            const int      ij = buf_ix[j];
            int rk = 0;
            for (int l = 0; l < nhi; ++l) {
                const unsigned fl2 = buf_fl[l];
                rk += (fl2 > fj) || (fl2 == fj && buf_ix[l] < ij);
            }
            if (rk < TOPK) s_kidx[rk] = ij;
        }
        kc = TOPK;
        __syncthreads();
    } else {
        // ---- Fallback: exact 3-level radix select over the segment ----
        unsigned prefix = 0, pmask = 0;
        int  above = 0;
        bool keepall = false, have_thr = false;

        for (int lvl = 0; lvl < 3; ++lvl) {
            const int      shift = (lvl == 0) ? 21 : (lvl == 1) ? 10 : 0;
            const unsigned mw    = (lvl == 2) ? 0x3FFu : 0x7FFu;

            for (int j = tid; j < 2048; j += BS) hist[j] = 0;
            if (tid == 0) s_found = 0;
            __syncthreads();

            for (int i = s0 + tid; i < s1; i += BS) {
                if (cmask[i] != 0) {
                    unsigned fl = flipf(scores[i]);
                    if ((fl & pmask) == prefix)
                        atomicAdd(&hist[(fl >> shift) & mw], 1);
                }
            }
            __syncthreads();

            if (tid < 32) {
                const int lane = tid;
                const int Kp   = TOPK - above;
                int cum = 0;
                for (int base = (int)mw; base >= 0; base -= 32) {
                    int bin = base - lane;
                    int c   = (bin >= 0) ? hist[bin] : 0;
                    int incl = c;
                    #pragma unroll
                    for (int off = 1; off < 32; off <<= 1) {
                        int v = __shfl_up_sync(0xffffffffu, incl, off);
                        if (lane >= off) incl += v;
                    }
                    unsigned bal = __ballot_sync(0xffffffffu, cum + incl >= Kp);
                    if (bal) {
                        int first = __ffs(bal) - 1;
                        if (lane == first) { s_bin = bin; s_above = cum + incl - c; s_found = 1; }
                        break;
                    }
                    cum += __shfl_sync(0xffffffffu, incl, 31);
                }
            }
            __syncthreads();

            if (!s_found) { keepall = true; break; }

            const int b = s_bin;
            above  += s_above;
            const int n = hist[b];
            prefix |= ((unsigned)b) << shift;
            pmask  |= mw << shift;
            __syncthreads();

            if (n <= CAP) {
                if (tid == 0) s_kcnt = 0;
                __syncthreads();
                for (int i = s0 + tid; i < s1; i += BS) {
                    if (cmask[i] != 0) {
                        unsigned fl = flipf(scores[i]);
                        if ((fl & pmask) == prefix) {
                            int p = atomicAdd(&s_kcnt, 1);
                            buf_fl[p] = fl; buf_ix[p] = i;
                        }
                    }
                }
                __syncthreads();
                const int nn = s_kcnt;
                const int r  = TOPK - 1 - above;
                for (int j = tid; j < nn; j += BS) {
                    unsigned fj = buf_fl[j]; int ij = buf_ix[j];
                    int rk = 0;
                    for (int l = 0; l < nn; ++l) {
                        unsigned fl2 = buf_fl[l];
                        rk += (fl2 > fj) || (fl2 == fj && buf_ix[l] < ij);
                    }
                    if (rk == r) { s_Tf = fj; s_Tix = ij; }
                }
                have_thr = true;
                __syncthreads();
                break;
            }
        }

        unsigned Tf; int Tix;
        if (keepall)       { Tf = 0u;   Tix = 0x7FFFFFFF; }
        else if (have_thr) { Tf = s_Tf; Tix = s_Tix; }
        else {
            const int m = TOPK - above;
            int last = -1;
            for (int t = 0; t < m; ++t) {
                if (tid == 0) s_minix = 0x7FFFFFFF;
                __syncthreads();
                for (int i = s0 + tid; i < s1; i += BS) {
                    if (cmask[i] != 0 && i > last) {
                        if (flipf(scores[i]) == prefix) atomicMin(&s_minix, i);
                    }
                }
                __syncthreads();
                last = s_minix;
                __syncthreads();
            }
            Tf = prefix; Tix = last;
        }

        if (tid == 0) s_kcnt = 0;
        __syncthreads();
        for (int i = s0 + tid; i < s1; i += BS) {
            if (cmask[i] != 0) {
                unsigned fl = flipf(scores[i]);
                if (fl > Tf || (fl == Tf && i <= Tix)) {
                    int p = atomicAdd(&s_kcnt, 1);
                    if (p < TOPK) s_kidx[p] = i;
                }
            }
        }
        __syncthreads();
        kc = min(s_kcnt, TOPK);
    }

    // ---- Segmented log-denominator over the <=32 kept logits + stop ----
    if (tid < kc) s_lv[tid] = logits[s_kidx[tid]];   // TEMP == 1.0
    __syncthreads();

    if (tid < 32) {
        float v = (tid < kc) ? s_lv[tid] : -INFINITY;
        float mx = v;
        #pragma unroll
        for (int off = 16; off; off >>= 1) mx = fmaxf(mx, __shfl_xor_sync(0xffffffffu, mx, off));
        float e = (tid < kc) ? expf(v - mx) : 0.0f;
        #pragma unroll
        for (int off = 16; off; off >>= 1) e += __shfl_xor_sync(0xffffffffu, e, off);
        if (tid == 0) {
            float st = stop[g];
            float ld;
            if (kc == 0) ld = st;
            else {
                float lse = logf(e) + mx;
                float a = fmaxf(lse, st), b2 = fminf(lse, st);
                ld = a + log1pf(expf(b2 - a));
            }
            s_ld = ld;
        }
    }
    __syncthreads();

    // Overwrite kept positions (fill already happened in the fused pass).
    if (tid < kc) out[s_kidx[tid]] = s_lv[tid] - s_ld;
}

extern "C" void kernel_launch(void* const* d_in, const int* in_sizes, int n_in,
                              void* d_out, int out_size) {
    const float* logits = (const float*)d_in[0];
    const float* scores = (const float*)d_in[1];
    const float* stop   = (const float*)d_in[2];
    const int*   batch  = (const int*)d_in[3];
    const int*   cmask  = (const int*)d_in[4];
    float* out = (float*)d_out;
    const int E = in_sizes[0];

    topk_kernel<<<NGRAPH, BS>>>(logits, scores, stop, cmask, batch, out, E);
}